// round 14
// baseline (speedup 1.0000x reference)
#include <cuda_runtime.h>
#include <cuda_bf16.h>
#include <cstdint>

// Problem constants (FiBiNet): B=1024, F=32, D=64, g=2
static constexpr int Bn   = 1024;
static constexpr int Pn   = 496;
static constexpr int KP   = 512;    // padded K for outgemm
static constexpr int EMB  = 2048;   // F*D
static constexpr int OUTN = 512;
static constexpr int OROW = 2560;   // EMB + OUTN

// Scratch (static __device__: allocation-guard safe)
__device__ __nv_bfloat16 g_xh[Bn * EMB];     // x hi
__device__ __nv_bfloat16 g_xl[Bn * EMB];     // x lo
__device__ __nv_bfloat16 g_WpTh[Pn * 4096];  // Wp^T hi, [p][e][d]
__device__ __nv_bfloat16 g_WpTl[Pn * 4096];  // Wp^T lo
__device__ __nv_bfloat16 g_dTh[Bn * KP];     // dots hi, [b][p], p padded
__device__ __nv_bfloat16 g_dTl[Bn * KP];     // dots lo
__device__ __nv_bfloat16 g_WoTh[OUTN * KP];  // Wo^T hi, [n][k]
__device__ __nv_bfloat16 g_WoTl[OUTN * KP];  // Wo^T lo

// ---------------------------------------------------------------------------
__device__ __forceinline__ void mma16816(float* d, const uint32_t* a, const uint32_t* b) {
    asm volatile(
        "mma.sync.aligned.m16n8k16.row.col.f32.bf16.bf16.f32 "
        "{%0,%1,%2,%3}, {%4,%5,%6,%7}, {%8,%9}, {%0,%1,%2,%3};"
        : "+f"(d[0]), "+f"(d[1]), "+f"(d[2]), "+f"(d[3])
        : "r"(a[0]), "r"(a[1]), "r"(a[2]), "r"(a[3]), "r"(b[0]), "r"(b[1]));
}

__device__ __forceinline__ void ldsm_x4(uint32_t* r, uint32_t saddr) {
    asm volatile("ldmatrix.sync.aligned.m8n8.x4.shared.b16 {%0,%1,%2,%3}, [%4];"
        : "=r"(r[0]), "=r"(r[1]), "=r"(r[2]), "=r"(r[3]) : "r"(saddr));
}

__device__ __forceinline__ void split_bf16(float v, __nv_bfloat16& h, __nv_bfloat16& l) {
    h = __float2bfloat16(v);
    l = __float2bfloat16(v - __bfloat162float(h));
}

__device__ __forceinline__ void cp_async16(void* sptr, const void* gptr) {
    uint32_t sa = (uint32_t)__cvta_generic_to_shared(sptr);
    asm volatile("cp.async.cg.shared.global [%0], [%1], 16;" :: "r"(sa), "l"(gptr));
}
#define CP_COMMIT() asm volatile("cp.async.commit_group;" ::: "memory")

// ---------------------------------------------------------------------------
// Fused prep (coarsened): blocks [0,256) xprep (8 float4/thread);
// [256,752) wp_prep; [752,1008) wo_prep+dpad
// ---------------------------------------------------------------------------
__global__ __launch_bounds__(256) void prep_kernel(
    const float* __restrict__ x, const float* __restrict__ Wp, const float* __restrict__ Wo)
{
    __shared__ float s[64 * 65];
    const int blk = blockIdx.x, t = threadIdx.x;

    if (blk < 256) {
        // ---- x -> bf16 hi/lo, 8 float4 per thread ----
        #pragma unroll
        for (int it = 0; it < 8; it++) {
            const int idx = blk * 2048 + it * 256 + t;
            const float4 v = ((const float4*)x)[idx];
            __nv_bfloat16 h[4], l[4];
            split_bf16(v.x, h[0], l[0]);
            split_bf16(v.y, h[1], l[1]);
            split_bf16(v.z, h[2], l[2]);
            split_bf16(v.w, h[3], l[3]);
            *(uint2*)(g_xh + (size_t)idx * 4) = *(uint2*)h;
            *(uint2*)(g_xl + (size_t)idx * 4) = *(uint2*)l;
        }
    } else if (blk < 752) {
        const int p = blk - 256;
        #pragma unroll
        for (int it = 0; it < 4; it++) {
            const int idx = t + 256 * it;
            const int d = idx >> 4, e4 = (idx & 15) * 4;
            const float4 v = *(const float4*)(Wp + (size_t)p * 4096 + d * 64 + e4);
            s[(e4 + 0) * 65 + d] = v.x;
            s[(e4 + 1) * 65 + d] = v.y;
            s[(e4 + 2) * 65 + d] = v.z;
            s[(e4 + 3) * 65 + d] = v.w;
        }
        __syncthreads();
        #pragma unroll
        for (int it = 0; it < 16; it++) {
            const int idx = t + 256 * it;
            const int e = idx >> 6, d = idx & 63;
            __nv_bfloat16 h, l;
            split_bf16(s[e * 65 + d], h, l);
            g_WpTh[(size_t)p * 4096 + idx] = h;
            g_WpTl[(size_t)p * 4096 + idx] = l;
        }
    } else {
        const int q = blk - 752;
        const int k0 = (q & 15) * 32, n0 = (q >> 4) * 32;
        float* s32 = s;
        #pragma unroll
        for (int it = 0; it < 4; it++) {
            const int idx = t + 256 * it;
            const int a = idx >> 5, b = idx & 31;
            s32[a * 33 + b] = (k0 + a < Pn) ? Wo[(size_t)(k0 + a) * OUTN + n0 + b] : 0.f;
        }
        __syncthreads();
        #pragma unroll
        for (int it = 0; it < 4; it++) {
            const int idx = t + 256 * it;
            const int n = idx >> 5, kk = idx & 31;
            __nv_bfloat16 h, l;
            split_bf16(s32[kk * 33 + n], h, l);
            g_WoTh[(size_t)(n0 + n) * KP + k0 + kk] = h;
            g_WoTl[(size_t)(n0 + n) * KP + k0 + kk] = l;
        }
        const int gid = q * 256 + t;
        if (gid < Bn * 16) {
            const int b = gid >> 4, c = gid & 15;
            g_dTh[(size_t)b * KP + Pn + c] = __float2bfloat16(0.f);
            g_dTl[(size_t)b * KP + Pn + c] = __float2bfloat16(0.f);
        }
    }
}

// ---------------------------------------------------------------------------
// SENet body (blocks 0..127 of the pair kernel): z -> a1 -> weights -> LN.
// ---------------------------------------------------------------------------
static constexpr int SXS = 2056;
static constexpr int SENET_SMEM = (8 * SXS + 4096 + 1024 + 256 + 64 + 64 + 8 + 8) * 4;

__device__ void senet_body(
    char* smemc, int bx,
    const float* __restrict__ x,  const float* __restrict__ W1, const float* __restrict__ b1,
    const float* __restrict__ W2, const float* __restrict__ b2,
    const float* __restrict__ ln_s, const float* __restrict__ ln_b, float* __restrict__ out)
{
    float* sdyn = (float*)smemc;
    float* sx   = sdyn;
    float* sW1  = sx + 8 * SXS;
    float* sz   = sW1 + 4096;
    float* sa1  = sz + 1024;
    float* wsum = sa1 + 256;
    float* wsq  = wsum + 64;
    float* mu_s = wsq + 64;
    float* rs_s = mu_s + 8;

    const int t = threadIdx.x, w = t >> 5, lane = t & 31;
    const int row0 = bx * 8;

    #pragma unroll
    for (int it = 0; it < 16; it++) {
        const int idx = t + 256 * it;
        const int row = idx >> 9, c4 = idx & 511;
        *(float4*)(sx + row * SXS + c4 * 4) =
            *(const float4*)(x + (size_t)(row0 + row) * EMB + c4 * 4);
    }
    #pragma unroll
    for (int it = 0; it < 4; it++) {
        const int idx = t + 256 * it;
        ((float4*)sW1)[idx] = ((const float4*)W1)[idx];
    }
    __syncthreads();

    #pragma unroll
    for (int ss = 0; ss < 2; ss++) {
        const int seg = 2 * lane + ss;
        const float* base = sx + w * SXS + seg * 32;
        float mx = -1e30f, sm = 0.f;
        #pragma unroll
        for (int it = 0; it < 32; it++) {
            const float v = base[(it + lane) & 31];
            mx = fmaxf(mx, v);
            sm += v;
        }
        const int f = seg >> 1, gi = seg & 1;
        sz[w * 128 + f * 4 + gi]     = mx;
        sz[w * 128 + f * 4 + 2 + gi] = sm * (1.0f / 32.0f);
    }
    __syncthreads();

    {
        const int row = t >> 5, o = t & 31;
        float acc = b1[o];
        #pragma unroll 8
        for (int k = 0; k < 128; k++) acc += sz[row * 128 + k] * sW1[k * 32 + o];
        sa1[row * 32 + o] = fmaxf(acc, 0.0f);
    }
    __syncthreads();

    float acc[8][8];
    #pragma unroll
    for (int c = 0; c < 8; c++)
        #pragma unroll
        for (int r = 0; r < 8; r++) acc[c][r] = 0.f;

    #pragma unroll 4
    for (int k = 0; k < 32; k++) {
        float w2v[8], a1v[8];
        #pragma unroll
        for (int c = 0; c < 8; c++) w2v[c] = W2[k * EMB + t + 256 * c];
        #pragma unroll
        for (int r = 0; r < 8; r++) a1v[r] = sa1[r * 32 + k];
        #pragma unroll
        for (int c = 0; c < 8; c++)
            #pragma unroll
            for (int r = 0; r < 8; r++) acc[c][r] += a1v[r] * w2v[c];
    }

    float sum[8], sq[8];
    #pragma unroll
    for (int r = 0; r < 8; r++) { sum[r] = 0.f; sq[r] = 0.f; }
    #pragma unroll
    for (int c = 0; c < 8; c++) {
        const int j = t + 256 * c;
        const float b2v = b2[j];
        #pragma unroll
        for (int r = 0; r < 8; r++) {
            const float xv = sx[r * SXS + j];
            const float s = xv * (1.0f + b2v + acc[c][r]);
            acc[c][r] = s;
            sum[r] += s;
            sq[r]  += s * s;
        }
    }
    #pragma unroll
    for (int r = 0; r < 8; r++) {
        float a = sum[r], b = sq[r];
        #pragma unroll
        for (int off = 16; off; off >>= 1) {
            a += __shfl_xor_sync(0xffffffffu, a, off);
            b += __shfl_xor_sync(0xffffffffu, b, off);
        }
        if (lane == 0) { wsum[w * 8 + r] = a; wsq[w * 8 + r] = b; }
    }
    __syncthreads();
    if (t < 8) {
        float a = 0.f, b = 0.f;
        #pragma unroll
        for (int ww = 0; ww < 8; ww++) { a += wsum[ww * 8 + t]; b += wsq[ww * 8 + t]; }
        const float mu = a * (1.0f / EMB);
        mu_s[t] = mu;
        rs_s[t] = rsqrtf(b * (1.0f / EMB) - mu * mu + 1e-6f);
    }
    __syncthreads();

    #pragma unroll
    for (int c = 0; c < 8; c++) {
        const int j = t + 256 * c;
        const float lsv = ln_s[j], lbv = ln_b[j];
        #pragma unroll
        for (int r = 0; r < 8; r++)
            out[(size_t)(row0 + r) * OROW + j] = (acc[c][r] - mu_s[r]) * rs_s[r] * lsv + lbv;
    }
}

// ---------------------------------------------------------------------------
// Pair body: i-grouped, cp.async depth-2 pipelined W ring, ldmatrix B-frags.
// ---------------------------------------------------------------------------
static constexpr int XPAD = 72;
static constexpr int WBUF = 2 * 64 * XPAD;                 // hi+lo per buffer (elems)
static constexpr int SM_W = 2 * 128 * XPAD;                // xi region size (elems)
static constexpr int PAIR_SMEM = (SM_W + 4 * WBUF) * 2;    // bytes (>= SENET_SMEM)

__device__ void pair_body(
    char* smem, int pbx, const float* __restrict__ x, const float* __restrict__ bp)
{
    __nv_bfloat16* sXh = (__nv_bfloat16*)smem;
    __nv_bfloat16* sXl = sXh + 128 * XPAD;
    __nv_bfloat16* sW  = sXh + SM_W;

    const int t = threadIdx.x, wid = t >> 5, lane = t & 31;
    const int k    = pbx & 15;
    const int b0   = ((pbx >> 4) & 7) * 128;
    const int half = pbx >> 7;

    const int r = lane >> 2, kq = (lane & 3) * 2;
    const int m0 = wid * 16;

    const int wrow0 = t >> 3, wch0 = t & 7;
    const int wrow1 = (t + 256) >> 3, wch1 = t & 7;

    const int lrow = lane & 7, lm = lane >> 3;
    const uint32_t sW_u32 = (uint32_t)__cvta_generic_to_shared(sW);
    const uint32_t lboff = (((lm >> 1) * 8 + lrow) * XPAD + (lm & 1) * 8) * 2;

    #pragma unroll 1
    for (int s = 0; s < 2; s++) {
        const int i = (s == 0) ? k : 30 - k;
        if (s == 1 && i == k) break;

        const int jstart = i + 1 + half;
        const int cnt = (jstart <= 31) ? ((31 - jstart) / 2 + 1) : 0;
        if (cnt == 0) { __syncthreads(); continue; }

        const int pbase = i * 31 - (i * (i - 1)) / 2 - i - 1;

        __syncthreads();

        #pragma unroll
        for (int pre = 0; pre < 2; pre++) {
            if (pre < cnt) {
                const int p = pbase + jstart + 2 * pre;
                __nv_bfloat16* dh = sW + pre * WBUF;
                __nv_bfloat16* dl = dh + 64 * XPAD;
                const __nv_bfloat16* gh = g_WpTh + (size_t)p * 4096;
                const __nv_bfloat16* gl = g_WpTl + (size_t)p * 4096;
                cp_async16(dh + wrow0 * XPAD + wch0 * 8, gh + wrow0 * 64 + wch0 * 8);
                cp_async16(dh + wrow1 * XPAD + wch1 * 8, gh + wrow1 * 64 + wch1 * 8);
                cp_async16(dl + wrow0 * XPAD + wch0 * 8, gl + wrow0 * 64 + wch0 * 8);
                cp_async16(dl + wrow1 * XPAD + wch1 * 8, gl + wrow1 * 64 + wch1 * 8);
                CP_COMMIT();
            }
        }

        #pragma unroll
        for (int it = 0; it < 4; it++) {
            const int idx = t + 256 * it;
            const int row = idx >> 3, ch = idx & 7;
            *(uint4*)(sXh + row * XPAD + ch * 8) =
                *(const uint4*)(g_xh + (size_t)(b0 + row) * EMB + i * 64 + ch * 8);
            *(uint4*)(sXl + row * XPAD + ch * 8) =
                *(const uint4*)(g_xl + (size_t)(b0 + row) * EMB + i * 64 + ch * 8);
        }
        __syncthreads();

        uint32_t ah[4][4], al[4][4];
        #pragma unroll
        for (int kt = 0; kt < 4; kt++) {
            const int kb = kt * 16 + kq;
            ah[kt][0] = *(const uint32_t*)(sXh + (m0 + r) * XPAD + kb);
            ah[kt][1] = *(const uint32_t*)(sXh + (m0 + r + 8) * XPAD + kb);
            ah[kt][2] = *(const uint32_t*)(sXh + (m0 + r) * XPAD + kb + 8);
            ah[kt][3] = *(const uint32_t*)(sXh + (m0 + r + 8) * XPAD + kb + 8);
            al[kt][0] = *(const uint32_t*)(sXl + (m0 + r) * XPAD + kb);
            al[kt][1] = *(const uint32_t*)(sXl + (m0 + r + 8) * XPAD + kb);
            al[kt][2] = *(const uint32_t*)(sXl + (m0 + r) * XPAD + kb + 8);
            al[kt][3] = *(const uint32_t*)(sXl + (m0 + r + 8) * XPAD + kb + 8);
        }

        #pragma unroll 1
        for (int kk = 0; kk < cnt; kk++) {
            const int j = jstart + 2 * kk;
            const int p = pbase + j;

            if (kk + 2 < cnt) {
                const int pn = pbase + j + 4;
                __nv_bfloat16* dh = sW + ((kk + 2) & 3) * WBUF;
                __nv_bfloat16* dl = dh + 64 * XPAD;
                const __nv_bfloat16* gh = g_WpTh + (size_t)pn * 4096;
                const __nv_bfloat16* gl = g_WpTl + (size_t)pn * 4096;
                cp_async16(dh + wrow0 * XPAD + wch0 * 8, gh + wrow0 * 64 + wch0 * 8);
                cp_async16(dh + wrow1 * XPAD + wch1 * 8, gh + wrow1 * 64 + wch1 * 8);
                cp_async16(dl + wrow0 * XPAD + wch0 * 8, gl + wrow0 * 64 + wch0 * 8);
                cp_async16(dl + wrow1 * XPAD + wch1 * 8, gl + wrow1 * 64 + wch1 * 8);
                CP_COMMIT();
            }
            const int ahead = cnt - 1 - kk;
            if (ahead >= 2)      asm volatile("cp.async.wait_group 2;" ::: "memory");
            else if (ahead == 1) asm volatile("cp.async.wait_group 1;" ::: "memory");
            else                 asm volatile("cp.async.wait_group 0;" ::: "memory");
            __syncthreads();

            const uint32_t bufh_s = sW_u32 + ((kk & 3) * WBUF) * 2;
            const uint32_t bufl_s = bufh_s + (64 * XPAD) * 2;

            float acc[8][4];
            #pragma unroll
            for (int nt = 0; nt < 8; nt++)
                #pragma unroll
                for (int q = 0; q < 4; q++) acc[nt][q] = 0.f;

            #pragma unroll
            for (int q = 0; q < 4; q++) {
                #pragma unroll
                for (int kt = 0; kt < 4; kt++) {
                    const uint32_t goff = lboff + (q * 16 * XPAD + kt * 16) * 2;
                    uint32_t bh4[4], bl4[4];
                    ldsm_x4(bh4, bufh_s + goff);
                    ldsm_x4(bl4, bufl_s + goff);
                    mma16816(acc[2 * q],     ah[kt], bh4);
                    mma16816(acc[2 * q],     ah[kt], bl4);
                    mma16816(acc[2 * q],     al[kt], bh4);
                    mma16816(acc[2 * q + 1], ah[kt], bh4 + 2);
                    mma16816(acc[2 * q + 1], ah[kt], bl4 + 2);
                    mma16816(acc[2 * q + 1], al[kt], bh4 + 2);
                }
            }

            const float* xj0p = x + (size_t)(b0 + m0 + r) * EMB + j * 64;
            const float* xj1p = x + (size_t)(b0 + m0 + r + 8) * EMB + j * 64;
            const float* bpp  = bp + (size_t)p * 64;
            float dot0 = 0.f, dot1 = 0.f;
            #pragma unroll
            for (int nt = 0; nt < 8; nt++) {
                const int c0 = nt * 8 + (lane & 3) * 2;
                const float2 bpv = *(const float2*)(bpp + c0);
                const float2 xj0 = *(const float2*)(xj0p + c0);
                const float2 xj1 = *(const float2*)(xj1p + c0);
                dot0 += (acc[nt][0] + bpv.x) * xj0.x + (acc[nt][1] + bpv.y) * xj0.y;
                dot1 += (acc[nt][2] + bpv.x) * xj1.x + (acc[nt][3] + bpv.y) * xj1.y;
            }
            dot0 += __shfl_xor_sync(0xffffffffu, dot0, 1);
            dot0 += __shfl_xor_sync(0xffffffffu, dot0, 2);
            dot1 += __shfl_xor_sync(0xffffffffu, dot1, 1);
            dot1 += __shfl_xor_sync(0xffffffffu, dot1, 2);
            if ((lane & 3) == 0) {
                __nv_bfloat16 h0, l0, h1, l1;
                split_bf16(dot0, h0, l0);
                split_bf16(dot1, h1, l1);
                const size_t o0 = (size_t)(b0 + m0 + r) * KP + p;
                const size_t o1 = (size_t)(b0 + m0 + r + 8) * KP + p;
                g_dTh[o0] = h0; g_dTl[o0] = l0;
                g_dTh[o1] = h1; g_dTl[o1] = l1;
            }
        }
    }
}

// Combined pair + senet kernel. Blocks [0,128) senet; [128,384) pair.
__global__ __launch_bounds__(256, 2) void pair_senet_kernel(
    const float* __restrict__ x, const float* __restrict__ bp,
    const float* __restrict__ W1, const float* __restrict__ b1,
    const float* __restrict__ W2, const float* __restrict__ b2,
    const float* __restrict__ ln_s, const float* __restrict__ ln_b,
    float* __restrict__ out)
{
    extern __shared__ char smem[];
    if (blockIdx.x < 128)
        senet_body(smem, blockIdx.x, x, W1, b1, W2, b2, ln_s, ln_b, out);
    else
        pair_body(smem, blockIdx.x - 128, x, bp);
}

// ---------------------------------------------------------------------------
// Kernel 3: outgemm (round-10 64x64 config), cp.async double-buffered +
// ldmatrix fragments.
// ---------------------------------------------------------------------------
static constexpr int OG_ARR   = 64 * 72;
static constexpr int OG_STAGE = 4 * OG_ARR;
static constexpr int OG_SMEM  = 2 * OG_STAGE * 2;

__global__ __launch_bounds__(256) void outgemm_mma_kernel(
    const float* __restrict__ bo, float* __restrict__ out)
{
    extern __shared__ char smemc[];
    __nv_bfloat16* sbase = (__nv_bfloat16*)smemc;

    const int t = threadIdx.x, wid = t >> 5, lane = t & 31;
    const int n0 = blockIdx.x * 64, m0 = blockIdx.y * 64;
    const int mwid = wid & 3, nwid = wid >> 2;
    const int r = lane >> 2;
    const int lrow = lane & 7, lm = lane >> 3;

    const uint32_t s_u32 = (uint32_t)__cvta_generic_to_shared(sbase);
    const uint32_t aoff = ((mwid * 16 + (lane & 7) + ((lane >> 3) & 1) * 8) * 72
                          + (lane >> 4) * 8) * 2;
    const uint32_t boff = ((nwid * 32 + (lm >> 1) * 8 + lrow) * 72 + (lm & 1) * 8) * 2;

    float acc[4][4];
    #pragma unroll
    for (int nt = 0; nt < 4; nt++)
        #pragma unroll
        for (int q = 0; q < 4; q++) acc[nt][q] = 0.f;

    auto issue = [&](int s) {
        const int k0 = s * 64;
        __nv_bfloat16* dA_h = sbase + (s & 1) * OG_STAGE;
        __nv_bfloat16* dA_l = dA_h + OG_ARR;
        __nv_bfloat16* dB_h = dA_l + OG_ARR;
        __nv_bfloat16* dB_l = dB_h + OG_ARR;
        #pragma unroll
        for (int it = 0; it < 2; it++) {
            const int idx = t + 256 * it;
            const int row = idx >> 3, ch = idx & 7;
            cp_async16(dA_h + row * 72 + ch * 8, g_dTh + (size_t)(m0 + row) * KP + k0 + ch * 8);
            cp_async16(dA_l + row * 72 + ch * 8, g_dTl + (size_t)(m0 + row) * KP + k0 + ch * 8);
            cp_async16(dB_h + row * 72 + ch * 8, g_WoTh + (size_t)(n0 + row) * KP + k0 + ch * 8);
            cp_async16(dB_l + row * 72 + ch * 8, g_WoTl + (size_t)(n0 + row) * KP + k0 + ch * 8);
        }
        CP_COMMIT();
    };

    issue(0);
    for (int s = 0; s < 8; s++) {
        if (s + 1 < 8) issue(s + 1);
        if (s + 1 < 8) asm volatile("cp.async.wait_group 1;" ::: "memory");
        else           asm volatile("cp.async.wait_group 0;" ::: "memory");
        __syncthreads();

        const uint32_t stg = s_u32 + ((s & 1) * OG_STAGE) * 2;
        const uint32_t sA_h = stg;
        const uint32_t sA_l = stg + OG_ARR * 2;
        const uint32_t sB_h = stg + 2 * OG_ARR * 2;
        const uint32_t sB_l = stg + 3 * OG_ARR * 2;

        #pragma unroll
        for (int kt = 0; kt < 4; kt++) {
            const uint32_t ka = (kt * 16) * 2;
            uint32_t ahf[4], alf[4];
            ldsm_x4(ahf, sA_h + aoff + ka);
            ldsm_x4(alf, sA_l + aoff + ka);
            #pragma unroll
            for (int q = 0; q < 2; q++) {
                const uint32_t goff = boff + (q * 16 * 72 + kt * 16) * 2;
                uint32_t bh4[4], bl4[4];
                ldsm_x4(bh4, sB_h + goff);
                ldsm_x4(bl4, sB_l + goff);
                mma16816(acc[2 * q],     ahf, bh4);
                mma16816(acc[2 * q],     ahf, bl4);
                mma16816(acc[2 * q],     alf, bh4);
                mma16816(acc[2 * q + 1], ahf, bh4 + 2);
                mma16816(acc[2 * q + 1], ahf, bl4 + 2);
                mma16816(acc[2 * q + 1], alf, bh4 + 2);
            }
        }
        __syncthreads();
    }

    #pragma unroll
    for (int nt = 0; nt < 4; nt++) {
        const int c = n0 + nwid * 32 + nt * 8 + (lane & 3) * 2;
        const float bo0 = bo[c], bo1 = bo[c + 1];
        const int mrow = m0 + mwid * 16 + r;
        float2 v0 = {acc[nt][0] + bo0, acc[nt][1] + bo1};
        float2 v1 = {acc[nt][2] + bo0, acc[nt][3] + bo1};
        *(float2*)(out + (size_t)mrow * OROW + EMB + c) = v0;
        *(float2*)(out + (size_t)(mrow + 8) * OROW + EMB + c) = v1;
    }
}

// ---------------------------------------------------------------------------
extern "C" void kernel_launch(void* const* d_in, const int* in_sizes, int n_in,
                              void* d_out, int out_size)
{
    const float* x    = (const float*)d_in[0];
    const float* W1   = (const float*)d_in[1];
    const float* b1   = (const float*)d_in[2];
    const float* W2   = (const float*)d_in[3];
    const float* b2   = (const float*)d_in[4];
    const float* ln_s = (const float*)d_in[5];
    const float* ln_b = (const float*)d_in[6];
    const float* Wp   = (const float*)d_in[7];
    const float* bp   = (const float*)d_in[8];
    const float* Wo   = (const float*)d_in[9];
    const float* bo   = (const float*)d_in[10];
    float* out = (float*)d_out;

    cudaFuncSetAttribute(pair_senet_kernel, cudaFuncAttributeMaxDynamicSharedMemorySize, PAIR_SMEM);
    cudaFuncSetAttribute(outgemm_mma_kernel, cudaFuncAttributeMaxDynamicSharedMemorySize, OG_SMEM);

    prep_kernel<<<1008, 256>>>(x, Wp, Wo);
    pair_senet_kernel<<<384, 256, PAIR_SMEM>>>(x, bp, W1, b1, W2, b2, ln_s, ln_b, out);
    outgemm_mma_kernel<<<dim3(OUTN / 64, Bn / 64), 256, OG_SMEM>>>(bo, out);
}

// round 16
// speedup vs baseline: 1.0503x; 1.0503x over previous
#include <cuda_runtime.h>
#include <cuda_bf16.h>
#include <cstdint>

// Problem constants (FiBiNet): B=1024, F=32, D=64, g=2
static constexpr int Bn   = 1024;
static constexpr int Pn   = 496;
static constexpr int KP   = 512;    // padded K for outgemm
static constexpr int EMB  = 2048;   // F*D
static constexpr int OUTN = 512;
static constexpr int OROW = 2560;   // EMB + OUTN

// Scratch (static __device__: allocation-guard safe)
__device__ __nv_bfloat16 g_xh[Bn * EMB];     // x hi
__device__ __nv_bfloat16 g_xl[Bn * EMB];     // x lo
__device__ __nv_bfloat16 g_WpTh[Pn * 4096];  // Wp^T hi, [p][e][d]
__device__ __nv_bfloat16 g_WpTl[Pn * 4096];  // Wp^T lo
__device__ __nv_bfloat16 g_dTh[Bn * KP];     // dots hi, [b][p], p padded
__device__ __nv_bfloat16 g_dTl[Bn * KP];     // dots lo
__device__ __nv_bfloat16 g_WoTh[OUTN * KP];  // Wo^T hi, [n][k]
__device__ __nv_bfloat16 g_WoTl[OUTN * KP];  // Wo^T lo

// ---------------------------------------------------------------------------
__device__ __forceinline__ void mma16816(float* d, const uint32_t* a, const uint32_t* b) {
    asm volatile(
        "mma.sync.aligned.m16n8k16.row.col.f32.bf16.bf16.f32 "
        "{%0,%1,%2,%3}, {%4,%5,%6,%7}, {%8,%9}, {%0,%1,%2,%3};"
        : "+f"(d[0]), "+f"(d[1]), "+f"(d[2]), "+f"(d[3])
        : "r"(a[0]), "r"(a[1]), "r"(a[2]), "r"(a[3]), "r"(b[0]), "r"(b[1]));
}

__device__ __forceinline__ void ldsm_x4(uint32_t* r, uint32_t saddr) {
    asm volatile("ldmatrix.sync.aligned.m8n8.x4.shared.b16 {%0,%1,%2,%3}, [%4];"
        : "=r"(r[0]), "=r"(r[1]), "=r"(r[2]), "=r"(r[3]) : "r"(saddr));
}

__device__ __forceinline__ void split_bf16(float v, __nv_bfloat16& h, __nv_bfloat16& l) {
    h = __float2bfloat16(v);
    l = __float2bfloat16(v - __bfloat162float(h));
}

__device__ __forceinline__ void cp_async16(void* sptr, const void* gptr) {
    uint32_t sa = (uint32_t)__cvta_generic_to_shared(sptr);
    asm volatile("cp.async.cg.shared.global [%0], [%1], 16;" :: "r"(sa), "l"(gptr));
}
#define CP_COMMIT() asm volatile("cp.async.commit_group;" ::: "memory")

// ---------------------------------------------------------------------------
// Fused prep (coarsened): blocks [0,256) xprep (8 float4/thread);
// [256,752) wp_prep; [752,1008) wo_prep+dpad
// ---------------------------------------------------------------------------
__global__ __launch_bounds__(256) void prep_kernel(
    const float* __restrict__ x, const float* __restrict__ Wp, const float* __restrict__ Wo)
{
    __shared__ float s[64 * 65];
    const int blk = blockIdx.x, t = threadIdx.x;

    if (blk < 256) {
        #pragma unroll
        for (int it = 0; it < 8; it++) {
            const int idx = blk * 2048 + it * 256 + t;
            const float4 v = ((const float4*)x)[idx];
            __nv_bfloat16 h[4], l[4];
            split_bf16(v.x, h[0], l[0]);
            split_bf16(v.y, h[1], l[1]);
            split_bf16(v.z, h[2], l[2]);
            split_bf16(v.w, h[3], l[3]);
            *(uint2*)(g_xh + (size_t)idx * 4) = *(uint2*)h;
            *(uint2*)(g_xl + (size_t)idx * 4) = *(uint2*)l;
        }
    } else if (blk < 752) {
        const int p = blk - 256;
        #pragma unroll
        for (int it = 0; it < 4; it++) {
            const int idx = t + 256 * it;
            const int d = idx >> 4, e4 = (idx & 15) * 4;
            const float4 v = *(const float4*)(Wp + (size_t)p * 4096 + d * 64 + e4);
            s[(e4 + 0) * 65 + d] = v.x;
            s[(e4 + 1) * 65 + d] = v.y;
            s[(e4 + 2) * 65 + d] = v.z;
            s[(e4 + 3) * 65 + d] = v.w;
        }
        __syncthreads();
        #pragma unroll
        for (int it = 0; it < 16; it++) {
            const int idx = t + 256 * it;
            const int e = idx >> 6, d = idx & 63;
            __nv_bfloat16 h, l;
            split_bf16(s[e * 65 + d], h, l);
            g_WpTh[(size_t)p * 4096 + idx] = h;
            g_WpTl[(size_t)p * 4096 + idx] = l;
        }
    } else {
        const int q = blk - 752;
        const int k0 = (q & 15) * 32, n0 = (q >> 4) * 32;
        float* s32 = s;
        #pragma unroll
        for (int it = 0; it < 4; it++) {
            const int idx = t + 256 * it;
            const int a = idx >> 5, b = idx & 31;
            s32[a * 33 + b] = (k0 + a < Pn) ? Wo[(size_t)(k0 + a) * OUTN + n0 + b] : 0.f;
        }
        __syncthreads();
        #pragma unroll
        for (int it = 0; it < 4; it++) {
            const int idx = t + 256 * it;
            const int n = idx >> 5, kk = idx & 31;
            __nv_bfloat16 h, l;
            split_bf16(s32[kk * 33 + n], h, l);
            g_WoTh[(size_t)(n0 + n) * KP + k0 + kk] = h;
            g_WoTl[(size_t)(n0 + n) * KP + k0 + kk] = l;
        }
        const int gid = q * 256 + t;
        if (gid < Bn * 16) {
            const int b = gid >> 4, c = gid & 15;
            g_dTh[(size_t)b * KP + Pn + c] = __float2bfloat16(0.f);
            g_dTl[(size_t)b * KP + Pn + c] = __float2bfloat16(0.f);
        }
    }
}

// ---------------------------------------------------------------------------
// Kernel 2: pairwise bilinear dots (round-10 config: i-grouped, cp.async
// depth-2 pipelined W ring, ldmatrix B-fragments).
// ---------------------------------------------------------------------------
static constexpr int XPAD = 72;
static constexpr int WBUF = 2 * 64 * XPAD;                 // hi+lo per buffer (elems)
static constexpr int SM_W = 2 * 128 * XPAD;                // xi region size (elems)
static constexpr int PAIR_SMEM = (SM_W + 4 * WBUF) * 2;    // bytes

__global__ __launch_bounds__(256, 2) void pair_mma_kernel(
    const float* __restrict__ x, const float* __restrict__ bp)
{
    extern __shared__ char smem[];
    __nv_bfloat16* sXh = (__nv_bfloat16*)smem;
    __nv_bfloat16* sXl = sXh + 128 * XPAD;
    __nv_bfloat16* sW  = sXh + SM_W;

    const int t = threadIdx.x, wid = t >> 5, lane = t & 31;
    const int k    = blockIdx.x;
    const int b0   = blockIdx.y * 128;
    const int half = blockIdx.z;

    const int r = lane >> 2, kq = (lane & 3) * 2;
    const int m0 = wid * 16;

    const int wrow0 = t >> 3, wch0 = t & 7;
    const int wrow1 = (t + 256) >> 3, wch1 = t & 7;

    const int lrow = lane & 7, lm = lane >> 3;
    const uint32_t sW_u32 = (uint32_t)__cvta_generic_to_shared(sW);
    const uint32_t lboff = (((lm >> 1) * 8 + lrow) * XPAD + (lm & 1) * 8) * 2;

    #pragma unroll 1
    for (int s = 0; s < 2; s++) {
        const int i = (s == 0) ? k : 30 - k;
        if (s == 1 && i == k) break;

        const int jstart = i + 1 + half;
        const int cnt = (jstart <= 31) ? ((31 - jstart) / 2 + 1) : 0;
        if (cnt == 0) { __syncthreads(); continue; }

        const int pbase = i * 31 - (i * (i - 1)) / 2 - i - 1;

        __syncthreads();

        #pragma unroll
        for (int pre = 0; pre < 2; pre++) {
            if (pre < cnt) {
                const int p = pbase + jstart + 2 * pre;
                __nv_bfloat16* dh = sW + pre * WBUF;
                __nv_bfloat16* dl = dh + 64 * XPAD;
                const __nv_bfloat16* gh = g_WpTh + (size_t)p * 4096;
                const __nv_bfloat16* gl = g_WpTl + (size_t)p * 4096;
                cp_async16(dh + wrow0 * XPAD + wch0 * 8, gh + wrow0 * 64 + wch0 * 8);
                cp_async16(dh + wrow1 * XPAD + wch1 * 8, gh + wrow1 * 64 + wch1 * 8);
                cp_async16(dl + wrow0 * XPAD + wch0 * 8, gl + wrow0 * 64 + wch0 * 8);
                cp_async16(dl + wrow1 * XPAD + wch1 * 8, gl + wrow1 * 64 + wch1 * 8);
                CP_COMMIT();
            }
        }

        #pragma unroll
        for (int it = 0; it < 4; it++) {
            const int idx = t + 256 * it;
            const int row = idx >> 3, ch = idx & 7;
            *(uint4*)(sXh + row * XPAD + ch * 8) =
                *(const uint4*)(g_xh + (size_t)(b0 + row) * EMB + i * 64 + ch * 8);
            *(uint4*)(sXl + row * XPAD + ch * 8) =
                *(const uint4*)(g_xl + (size_t)(b0 + row) * EMB + i * 64 + ch * 8);
        }
        __syncthreads();

        uint32_t ah[4][4], al[4][4];
        #pragma unroll
        for (int kt = 0; kt < 4; kt++) {
            const int kb = kt * 16 + kq;
            ah[kt][0] = *(const uint32_t*)(sXh + (m0 + r) * XPAD + kb);
            ah[kt][1] = *(const uint32_t*)(sXh + (m0 + r + 8) * XPAD + kb);
            ah[kt][2] = *(const uint32_t*)(sXh + (m0 + r) * XPAD + kb + 8);
            ah[kt][3] = *(const uint32_t*)(sXh + (m0 + r + 8) * XPAD + kb + 8);
            al[kt][0] = *(const uint32_t*)(sXl + (m0 + r) * XPAD + kb);
            al[kt][1] = *(const uint32_t*)(sXl + (m0 + r + 8) * XPAD + kb);
            al[kt][2] = *(const uint32_t*)(sXl + (m0 + r) * XPAD + kb + 8);
            al[kt][3] = *(const uint32_t*)(sXl + (m0 + r + 8) * XPAD + kb + 8);
        }

        #pragma unroll 1
        for (int kk = 0; kk < cnt; kk++) {
            const int j = jstart + 2 * kk;
            const int p = pbase + j;

            if (kk + 2 < cnt) {
                const int pn = pbase + j + 4;
                __nv_bfloat16* dh = sW + ((kk + 2) & 3) * WBUF;
                __nv_bfloat16* dl = dh + 64 * XPAD;
                const __nv_bfloat16* gh = g_WpTh + (size_t)pn * 4096;
                const __nv_bfloat16* gl = g_WpTl + (size_t)pn * 4096;
                cp_async16(dh + wrow0 * XPAD + wch0 * 8, gh + wrow0 * 64 + wch0 * 8);
                cp_async16(dh + wrow1 * XPAD + wch1 * 8, gh + wrow1 * 64 + wch1 * 8);
                cp_async16(dl + wrow0 * XPAD + wch0 * 8, gl + wrow0 * 64 + wch0 * 8);
                cp_async16(dl + wrow1 * XPAD + wch1 * 8, gl + wrow1 * 64 + wch1 * 8);
                CP_COMMIT();
            }
            const int ahead = cnt - 1 - kk;
            if (ahead >= 2)      asm volatile("cp.async.wait_group 2;" ::: "memory");
            else if (ahead == 1) asm volatile("cp.async.wait_group 1;" ::: "memory");
            else                 asm volatile("cp.async.wait_group 0;" ::: "memory");
            __syncthreads();

            const uint32_t bufh_s = sW_u32 + ((kk & 3) * WBUF) * 2;
            const uint32_t bufl_s = bufh_s + (64 * XPAD) * 2;

            float acc[8][4];
            #pragma unroll
            for (int nt = 0; nt < 8; nt++)
                #pragma unroll
                for (int q = 0; q < 4; q++) acc[nt][q] = 0.f;

            #pragma unroll
            for (int q = 0; q < 4; q++) {
                #pragma unroll
                for (int kt = 0; kt < 4; kt++) {
                    const uint32_t goff = lboff + (q * 16 * XPAD + kt * 16) * 2;
                    uint32_t bh4[4], bl4[4];
                    ldsm_x4(bh4, bufh_s + goff);
                    ldsm_x4(bl4, bufl_s + goff);
                    mma16816(acc[2 * q],     ah[kt], bh4);
                    mma16816(acc[2 * q],     ah[kt], bl4);
                    mma16816(acc[2 * q],     al[kt], bh4);
                    mma16816(acc[2 * q + 1], ah[kt], bh4 + 2);
                    mma16816(acc[2 * q + 1], ah[kt], bl4 + 2);
                    mma16816(acc[2 * q + 1], al[kt], bh4 + 2);
                }
            }

            const float* xj0p = x + (size_t)(b0 + m0 + r) * EMB + j * 64;
            const float* xj1p = x + (size_t)(b0 + m0 + r + 8) * EMB + j * 64;
            const float* bpp  = bp + (size_t)p * 64;
            float dot0 = 0.f, dot1 = 0.f;
            #pragma unroll
            for (int nt = 0; nt < 8; nt++) {
                const int c0 = nt * 8 + (lane & 3) * 2;
                const float2 bpv = *(const float2*)(bpp + c0);
                const float2 xj0 = *(const float2*)(xj0p + c0);
                const float2 xj1 = *(const float2*)(xj1p + c0);
                dot0 += (acc[nt][0] + bpv.x) * xj0.x + (acc[nt][1] + bpv.y) * xj0.y;
                dot1 += (acc[nt][2] + bpv.x) * xj1.x + (acc[nt][3] + bpv.y) * xj1.y;
            }
            dot0 += __shfl_xor_sync(0xffffffffu, dot0, 1);
            dot0 += __shfl_xor_sync(0xffffffffu, dot0, 2);
            dot1 += __shfl_xor_sync(0xffffffffu, dot1, 1);
            dot1 += __shfl_xor_sync(0xffffffffu, dot1, 2);
            if ((lane & 3) == 0) {
                __nv_bfloat16 h0, l0, h1, l1;
                split_bf16(dot0, h0, l0);
                split_bf16(dot1, h1, l1);
                const size_t o0 = (size_t)(b0 + m0 + r) * KP + p;
                const size_t o1 = (size_t)(b0 + m0 + r + 8) * KP + p;
                g_dTh[o0] = h0; g_dTl[o0] = l0;
                g_dTh[o1] = h1; g_dTl[o1] = l1;
            }
        }
    }
}

// ---------------------------------------------------------------------------
// Tail kernel: blocks [0,128) = fused SENet+LN; [128,256) = outgemm (64x64,
// cp.async double-buffered, ldmatrix). Independent stages co-resident.
// ---------------------------------------------------------------------------
static constexpr int SXS = 2056;
static constexpr int OG_ARR   = 64 * 72;
static constexpr int OG_STAGE = 4 * OG_ARR;
static constexpr int TAIL_SMEM = (8 * SXS + 4096 + 1024 + 256 + 64 + 64 + 8 + 8) * 4;  // 87872 B

__device__ void senet_body(
    char* smemc, int bx,
    const float* __restrict__ x,  const float* __restrict__ W1, const float* __restrict__ b1,
    const float* __restrict__ W2, const float* __restrict__ b2,
    const float* __restrict__ ln_s, const float* __restrict__ ln_b, float* __restrict__ out)
{
    float* sdyn = (float*)smemc;
    float* sx   = sdyn;
    float* sW1  = sx + 8 * SXS;
    float* sz   = sW1 + 4096;
    float* sa1  = sz + 1024;
    float* wsum = sa1 + 256;
    float* wsq  = wsum + 64;
    float* mu_s = wsq + 64;
    float* rs_s = mu_s + 8;

    const int t = threadIdx.x, w = t >> 5, lane = t & 31;
    const int row0 = bx * 8;

    #pragma unroll
    for (int it = 0; it < 16; it++) {
        const int idx = t + 256 * it;
        const int row = idx >> 9, c4 = idx & 511;
        *(float4*)(sx + row * SXS + c4 * 4) =
            *(const float4*)(x + (size_t)(row0 + row) * EMB + c4 * 4);
    }
    #pragma unroll
    for (int it = 0; it < 4; it++) {
        const int idx = t + 256 * it;
        ((float4*)sW1)[idx] = ((const float4*)W1)[idx];
    }
    __syncthreads();

    #pragma unroll
    for (int ss = 0; ss < 2; ss++) {
        const int seg = 2 * lane + ss;
        const float* base = sx + w * SXS + seg * 32;
        float mx = -1e30f, sm = 0.f;
        #pragma unroll
        for (int it = 0; it < 32; it++) {
            const float v = base[(it + lane) & 31];
            mx = fmaxf(mx, v);
            sm += v;
        }
        const int f = seg >> 1, gi = seg & 1;
        sz[w * 128 + f * 4 + gi]     = mx;
        sz[w * 128 + f * 4 + 2 + gi] = sm * (1.0f / 32.0f);
    }
    __syncthreads();

    {
        const int row = t >> 5, o = t & 31;
        float acc = b1[o];
        #pragma unroll 8
        for (int k = 0; k < 128; k++) acc += sz[row * 128 + k] * sW1[k * 32 + o];
        sa1[row * 32 + o] = fmaxf(acc, 0.0f);
    }
    __syncthreads();

    float acc[8][8];
    #pragma unroll
    for (int c = 0; c < 8; c++)
        #pragma unroll
        for (int r = 0; r < 8; r++) acc[c][r] = 0.f;

    #pragma unroll 4
    for (int k = 0; k < 32; k++) {
        float w2v[8], a1v[8];
        #pragma unroll
        for (int c = 0; c < 8; c++) w2v[c] = W2[k * EMB + t + 256 * c];
        #pragma unroll
        for (int r = 0; r < 8; r++) a1v[r] = sa1[r * 32 + k];
        #pragma unroll
        for (int c = 0; c < 8; c++)
            #pragma unroll
            for (int r = 0; r < 8; r++) acc[c][r] += a1v[r] * w2v[c];
    }

    float sum[8], sq[8];
    #pragma unroll
    for (int r = 0; r < 8; r++) { sum[r] = 0.f; sq[r] = 0.f; }
    #pragma unroll
    for (int c = 0; c < 8; c++) {
        const int j = t + 256 * c;
        const float b2v = b2[j];
        #pragma unroll
        for (int r = 0; r < 8; r++) {
            const float xv = sx[r * SXS + j];
            const float s = xv * (1.0f + b2v + acc[c][r]);
            acc[c][r] = s;
            sum[r] += s;
            sq[r]  += s * s;
        }
    }
    #pragma unroll
    for (int r = 0; r < 8; r++) {
        float a = sum[r], b = sq[r];
        #pragma unroll
        for (int off = 16; off; off >>= 1) {
            a += __shfl_xor_sync(0xffffffffu, a, off);
            b += __shfl_xor_sync(0xffffffffu, b, off);
        }
        if (lane == 0) { wsum[w * 8 + r] = a; wsq[w * 8 + r] = b; }
    }
    __syncthreads();
    if (t < 8) {
        float a = 0.f, b = 0.f;
        #pragma unroll
        for (int ww = 0; ww < 8; ww++) { a += wsum[ww * 8 + t]; b += wsq[ww * 8 + t]; }
        const float mu = a * (1.0f / EMB);
        mu_s[t] = mu;
        rs_s[t] = rsqrtf(b * (1.0f / EMB) - mu * mu + 1e-6f);
    }
    __syncthreads();

    #pragma unroll
    for (int c = 0; c < 8; c++) {
        const int j = t + 256 * c;
        const float lsv = ln_s[j], lbv = ln_b[j];
        #pragma unroll
        for (int r = 0; r < 8; r++)
            out[(size_t)(row0 + r) * OROW + j] = (acc[c][r] - mu_s[r]) * rs_s[r] * lsv + lbv;
    }
}

__device__ void outgemm_body(
    char* smemc, int bx, const float* __restrict__ bo, float* __restrict__ out)
{
    __nv_bfloat16* sbase = (__nv_bfloat16*)smemc;

    const int t = threadIdx.x, wid = t >> 5, lane = t & 31;
    const int n0 = (bx & 7) * 64, m0 = (bx >> 3) * 64;
    const int mwid = wid & 3, nwid = wid >> 2;
    const int r = lane >> 2;
    const int lrow = lane & 7, lm = lane >> 3;

    const uint32_t s_u32 = (uint32_t)__cvta_generic_to_shared(sbase);
    const uint32_t aoff = ((mwid * 16 + (lane & 7) + ((lane >> 3) & 1) * 8) * 72
                          + (lane >> 4) * 8) * 2;
    const uint32_t boff = ((nwid * 32 + (lm >> 1) * 8 + lrow) * 72 + (lm & 1) * 8) * 2;

    float acc[4][4];
    #pragma unroll
    for (int nt = 0; nt < 4; nt++)
        #pragma unroll
        for (int q = 0; q < 4; q++) acc[nt][q] = 0.f;

    auto issue = [&](int s) {
        const int k0 = s * 64;
        __nv_bfloat16* dA_h = sbase + (s & 1) * OG_STAGE;
        __nv_bfloat16* dA_l = dA_h + OG_ARR;
        __nv_bfloat16* dB_h = dA_l + OG_ARR;
        __nv_bfloat16* dB_l = dB_h + OG_ARR;
        #pragma unroll
        for (int it = 0; it < 2; it++) {
            const int idx = t + 256 * it;
            const int row = idx >> 3, ch = idx & 7;
            cp_async16(dA_h + row * 72 + ch * 8, g_dTh + (size_t)(m0 + row) * KP + k0 + ch * 8);
            cp_async16(dA_l + row * 72 + ch * 8, g_dTl + (size_t)(m0 + row) * KP + k0 + ch * 8);
            cp_async16(dB_h + row * 72 + ch * 8, g_WoTh + (size_t)(n0 + row) * KP + k0 + ch * 8);
            cp_async16(dB_l + row * 72 + ch * 8, g_WoTl + (size_t)(n0 + row) * KP + k0 + ch * 8);
        }
        CP_COMMIT();
    };

    issue(0);
    for (int s = 0; s < 8; s++) {
        if (s + 1 < 8) issue(s + 1);
        if (s + 1 < 8) asm volatile("cp.async.wait_group 1;" ::: "memory");
        else           asm volatile("cp.async.wait_group 0;" ::: "memory");
        __syncthreads();

        const uint32_t stg = s_u32 + ((s & 1) * OG_STAGE) * 2;
        const uint32_t sA_h = stg;
        const uint32_t sA_l = stg + OG_ARR * 2;
        const uint32_t sB_h = stg + 2 * OG_ARR * 2;
        const uint32_t sB_l = stg + 3 * OG_ARR * 2;

        #pragma unroll
        for (int kt = 0; kt < 4; kt++) {
            const uint32_t ka = (kt * 16) * 2;
            uint32_t ahf[4], alf[4];
            ldsm_x4(ahf, sA_h + aoff + ka);
            ldsm_x4(alf, sA_l + aoff + ka);
            #pragma unroll
            for (int q = 0; q < 2; q++) {
                const uint32_t goff = boff + (q * 16 * 72 + kt * 16) * 2;
                uint32_t bh4[4], bl4[4];
                ldsm_x4(bh4, sB_h + goff);
                ldsm_x4(bl4, sB_l + goff);
                mma16816(acc[2 * q],     ahf, bh4);
                mma16816(acc[2 * q],     ahf, bl4);
                mma16816(acc[2 * q],     alf, bh4);
                mma16816(acc[2 * q + 1], ahf, bh4 + 2);
                mma16816(acc[2 * q + 1], ahf, bl4 + 2);
                mma16816(acc[2 * q + 1], alf, bh4 + 2);
            }
        }
        __syncthreads();
    }

    #pragma unroll
    for (int nt = 0; nt < 4; nt++) {
        const int c = n0 + nwid * 32 + nt * 8 + (lane & 3) * 2;
        const float bo0 = bo[c], bo1 = bo[c + 1];
        const int mrow = m0 + mwid * 16 + r;
        float2 v0 = {acc[nt][0] + bo0, acc[nt][1] + bo1};
        float2 v1 = {acc[nt][2] + bo0, acc[nt][3] + bo1};
        *(float2*)(out + (size_t)mrow * OROW + EMB + c) = v0;
        *(float2*)(out + (size_t)(mrow + 8) * OROW + EMB + c) = v1;
    }
}

__global__ __launch_bounds__(256) void tail_kernel(
    const float* __restrict__ x,  const float* __restrict__ W1, const float* __restrict__ b1,
    const float* __restrict__ W2, const float* __restrict__ b2,
    const float* __restrict__ ln_s, const float* __restrict__ ln_b,
    const float* __restrict__ bo, float* __restrict__ out)
{
    extern __shared__ char smemc[];
    if (blockIdx.x < 128)
        senet_body(smemc, blockIdx.x, x, W1, b1, W2, b2, ln_s, ln_b, out);
    else
        outgemm_body(smemc, blockIdx.x - 128, bo, out);
}

// ---------------------------------------------------------------------------
extern "C" void kernel_launch(void* const* d_in, const int* in_sizes, int n_in,
                              void* d_out, int out_size)
{
    const float* x    = (const float*)d_in[0];
    const float* W1   = (const float*)d_in[1];
    const float* b1   = (const float*)d_in[2];
    const float* W2   = (const float*)d_in[3];
    const float* b2   = (const float*)d_in[4];
    const float* ln_s = (const float*)d_in[5];
    const float* ln_b = (const float*)d_in[6];
    const float* Wp   = (const float*)d_in[7];
    const float* bp   = (const float*)d_in[8];
    const float* Wo   = (const float*)d_in[9];
    const float* bo   = (const float*)d_in[10];
    float* out = (float*)d_out;

    cudaFuncSetAttribute(pair_mma_kernel, cudaFuncAttributeMaxDynamicSharedMemorySize, PAIR_SMEM);
    cudaFuncSetAttribute(tail_kernel, cudaFuncAttributeMaxDynamicSharedMemorySize, TAIL_SMEM);

    prep_kernel<<<1008, 256>>>(x, Wp, Wo);
    pair_mma_kernel<<<dim3(16, Bn / 128, 2), 256, PAIR_SMEM>>>(x, bp);
    tail_kernel<<<256, 256, TAIL_SMEM>>>(x, W1, b1, W2, b2, ln_s, ln_b, bo, out);
}